// round 7
// baseline (speedup 1.0000x reference)
#include <cuda_runtime.h>
#include <cuda_bf16.h>
#include <math.h>
#include <stdint.h>

#define Bsz 2
#define S 2048
#define H 16
#define KV 8
#define HD 64
#define WINDOW 512
#define M_TOT (Bsz * S)      // 4096

__device__ float g_Q[M_TOT * (H * HD)];    // [b*s, 1024]
__device__ float g_K[M_TOT * (KV * HD)];   // [b*s, 512]
__device__ float g_V[M_TOT * (KV * HD)];
__device__ float g_O[M_TOT * (H * HD)];
__device__ float2 g_rope[S * 32];          // (cos,sin) per (t,f)

__device__ __forceinline__ uint32_t f2tf(float f) {
    uint32_t r;
    asm("cvt.rna.tf32.f32 %0, %1;" : "=r"(r) : "f"(f));
    return r;
}

__device__ __forceinline__ void mma_tf32(float c[4],
    uint32_t a0, uint32_t a1, uint32_t a2, uint32_t a3, uint32_t b0, uint32_t b1) {
    asm volatile(
        "mma.sync.aligned.m16n8k8.row.col.f32.tf32.tf32.f32 "
        "{%0,%1,%2,%3}, {%4,%5,%6,%7}, {%8,%9}, {%0,%1,%2,%3};"
        : "+f"(c[0]), "+f"(c[1]), "+f"(c[2]), "+f"(c[3])
        : "r"(a0), "r"(a1), "r"(a2), "r"(a3), "r"(b0), "r"(b1));
}

// ---------------------------------------------------------------------------
// RoPE table + in-place apply
// ---------------------------------------------------------------------------
__global__ void rope_init_kernel() {
    const int idx = blockIdx.x * 256 + threadIdx.x;  // 65536
    const int t = idx >> 5, f = idx & 31;
    const float invf = expf(-logf(10000.0f) * (float)f * (1.0f / 32.0f));
    float sv, cv;
    sincosf((float)t * invf, &sv, &cv);
    g_rope[idx] = make_float2(cv, sv);
}

__global__ __launch_bounds__(256) void rope_apply_kernel() {
    const int idx = blockIdx.x * 256 + threadIdx.x;
    float* buf; int ld, p;
    if (idx < M_TOT * 512) { buf = g_Q; ld = 1024; p = idx; }
    else                   { buf = g_K; ld = 512;  p = idx - M_TOT * 512; }
    const int pph = ld >> 1;
    const int row = p / pph;
    const int q = p - row * pph;
    const int h = q >> 5, f = q & 31;
    const int t = row & (S - 1);
    float* base = buf + (size_t)row * ld + h * 64 + f;
    const float x = base[0], y = base[32];
    const float2 cs = g_rope[t * 32 + f];
    base[0]  = x * cs.x - y * cs.y;
    base[32] = y * cs.x + x * cs.y;
}

// ---------------------------------------------------------------------------
// tf32 GEMM core (unchanged): 128x128 tile, BK=16, 256 threads
// ---------------------------------------------------------------------------
__device__ __forceinline__ void gemm_tf32_core(
    const float* __restrict__ A0,
    const float* __restrict__ Bp, int ldb, int colbase,
    uint2 (*sA)[2][512], uint2 (*sB)[2][512],
    float c[4][4][4])
{
    const int tid = threadIdx.x, lane = tid & 31, warp = tid >> 5;
    const int wm = warp >> 2, wn = warp & 3;

#pragma unroll
    for (int m = 0; m < 4; m++)
#pragma unroll
        for (int n = 0; n < 4; n++)
#pragma unroll
            for (int q = 0; q < 4; q++) c[m][n][q] = 0.f;

    const int am = tid >> 1, akc = tid & 1;
    const float* ap = A0 + (size_t)am * 1024 + akc * 8;
    const int bc = tid & 3, bkc = (tid >> 2) & 1, bn = (tid >> 3) * 4;
    const float* bp = Bp + (size_t)(bkc * 8 + bc) * ldb + colbase + bn;

    float la[8], lb[8];
#define LOAD_G(k0) do { \
        float4 a0_ = *(const float4*)(ap + (k0)); \
        float4 a1_ = *(const float4*)(ap + (k0) + 4); \
        la[0]=a0_.x; la[1]=a0_.y; la[2]=a0_.z; la[3]=a0_.w; \
        la[4]=a1_.x; la[5]=a1_.y; la[6]=a1_.z; la[7]=a1_.w; \
        float4 b0_ = *(const float4*)(bp + (size_t)(k0) * ldb); \
        float4 b1_ = *(const float4*)(bp + (size_t)((k0) + 4) * ldb); \
        lb[0]=b0_.x; lb[1]=b0_.y; lb[2]=b0_.z; lb[3]=b0_.w; \
        lb[4]=b1_.x; lb[5]=b1_.y; lb[6]=b1_.z; lb[7]=b1_.w; \
    } while (0)
#define STS_T(st) do { \
        uint2* a_ = sA[st][akc] + am * 4; \
        a_[0] = make_uint2(f2tf(la[0]), f2tf(la[4])); \
        a_[1] = make_uint2(f2tf(la[1]), f2tf(la[5])); \
        a_[2] = make_uint2(f2tf(la[2]), f2tf(la[6])); \
        a_[3] = make_uint2(f2tf(la[3]), f2tf(la[7])); \
        uint2* b_ = sB[st][bkc]; \
        b_[(bn + 0) * 4 + bc] = make_uint2(f2tf(lb[0]), f2tf(lb[4])); \
        b_[(bn + 1) * 4 + bc] = make_uint2(f2tf(lb[1]), f2tf(lb[5])); \
        b_[(bn + 2) * 4 + bc] = make_uint2(f2tf(lb[2]), f2tf(lb[6])); \
        b_[(bn + 3) * 4 + bc] = make_uint2(f2tf(lb[3]), f2tf(lb[7])); \
    } while (0)

    LOAD_G(0);
    STS_T(0);
    __syncthreads();

    for (int kt = 0; kt < 64; kt++) {
        const int st = kt & 1;
        if (kt < 63) LOAD_G((kt + 1) * 16);
#pragma unroll
        for (int kc = 0; kc < 2; kc++) {
            const uint2* a = sA[st][kc];
            const uint2* b = sB[st][kc];
            uint2 alo[4], ahi[4], bf[4];
#pragma unroll
            for (int m = 0; m < 4; m++) {
                alo[m] = a[wm * 256 + m * 64 + lane];
                ahi[m] = a[wm * 256 + m * 64 + 32 + lane];
            }
#pragma unroll
            for (int n = 0; n < 4; n++)
                bf[n] = b[wn * 128 + n * 32 + lane];
#pragma unroll
            for (int m = 0; m < 4; m++)
#pragma unroll
                for (int n = 0; n < 4; n++)
                    mma_tf32(c[m][n], alo[m].x, ahi[m].x, alo[m].y, ahi[m].y,
                             bf[n].x, bf[n].y);
        }
        if (kt < 63) STS_T(st ^ 1);
        __syncthreads();
    }
#undef LOAD_G
#undef STS_T
}

__device__ __forceinline__ void gemm_store(
    float* dst, int dld, int mrow0, int colbase, float c[4][4][4])
{
    const int lane = threadIdx.x & 31, warp = threadIdx.x >> 5;
    const int wm = warp >> 2, wn = warp & 3;
#pragma unroll
    for (int m = 0; m < 4; m++) {
        const int r0 = mrow0 + wm * 64 + m * 16 + (lane >> 2);
#pragma unroll
        for (int n = 0; n < 4; n++) {
            const int gc = colbase + wn * 32 + n * 8 + 2 * (lane & 3);
            *(float2*)&dst[(size_t)r0 * dld + gc]       = make_float2(c[m][n][0], c[m][n][1]);
            *(float2*)&dst[(size_t)(r0 + 8) * dld + gc] = make_float2(c[m][n][2], c[m][n][3]);
        }
    }
}

__global__ __launch_bounds__(256) void qkv_tf32_kernel(
    const float* __restrict__ X, const float* __restrict__ Wq,
    const float* __restrict__ Wk, const float* __restrict__ Wv)
{
    __shared__ uint2 sA[2][2][512];
    __shared__ uint2 sB[2][2][512];
    const int bx = blockIdx.x;
    const int mrow0 = blockIdx.y * 128;
    const float* Bp; int ldb; float* dst; int dld; int colbase;
    if (bx < 8)       { Bp = Wq; ldb = 1024; dst = g_Q; dld = 1024; colbase = bx * 128; }
    else if (bx < 12) { Bp = Wk; ldb = 512;  dst = g_K; dld = 512;  colbase = (bx - 8) * 128; }
    else              { Bp = Wv; ldb = 512;  dst = g_V; dld = 512;  colbase = (bx - 12) * 128; }
    float c[4][4][4];
    gemm_tf32_core(X + (size_t)mrow0 * 1024, Bp, ldb, colbase, sA, sB, c);
    gemm_store(dst, dld, mrow0, colbase, c);
}

__global__ __launch_bounds__(256) void outproj_tf32_kernel(
    const float* __restrict__ Wo, float* __restrict__ out)
{
    __shared__ uint2 sA[2][2][512];
    __shared__ uint2 sB[2][2][512];
    const int colbase = blockIdx.x * 128;
    const int mrow0 = blockIdx.y * 128;
    float c[4][4][4];
    gemm_tf32_core(g_O + (size_t)mrow0 * 1024, Wo, 1024, colbase, sA, sB, c);
    gemm_store(out, 1024, mrow0, colbase, c);
}

// ---------------------------------------------------------------------------
// Attention v3: tf32 MMA for QK^T and PV. 64x64 q-tile, 4 warps (128 thr).
// Warp w owns rows 16w..16w+15 of S and O (m16n8k8 fragments).
//  sQ[kc][q*4+i]  = (Q[q][kc*8+i], Q[q][kc*8+4+i])            A pairs (d,d+4)
//  sKV K: [kc][k*4+i] = (K[k][kc*8+i], K[k][kc*8+4+i])        B pairs (d,d+4)
//  sKV V: [kc][d*4+c] = (V[kc*8+c][d], V[kc*8+c+4][d])        B pairs (key,key+4)
//  sP[row][col] f32, pad 68 -> conflict-free A-frag scalar loads.
// ---------------------------------------------------------------------------
__global__ __launch_bounds__(128) void attn_kernel()
{
    __shared__ uint2 sQ[8][256];
    __shared__ uint2 sKV[8][256];
    __shared__ float sP[64][68];

    const int bh = blockIdx.y;
    const int b = bh >> 4, h = bh & 15, kvh = h >> 1;
    const int q0 = blockIdx.x * 64;
    const int tid = threadIdx.x;
    const int lane = tid & 31, warp = tid >> 5;
    const int r0 = warp * 16 + (lane >> 2);   // local row for c0/c1 (c2/c3: +8)
    const int cq = lane & 3;

    // load Q tile (prescaled, tf32 pairs)
#pragma unroll
    for (int it = 0; it < 4; it++) {
        const int item = it * 128 + tid;
        const int dc = item & 7, qq = item >> 3;
        const float* p = g_Q + ((size_t)(b * S + q0 + qq)) * 1024 + h * 64 + dc * 8;
        const float4 v0 = *(const float4*)p;
        const float4 v1 = *(const float4*)(p + 4);
        sQ[dc][qq * 4 + 0] = make_uint2(f2tf(v0.x * 0.125f), f2tf(v1.x * 0.125f));
        sQ[dc][qq * 4 + 1] = make_uint2(f2tf(v0.y * 0.125f), f2tf(v1.y * 0.125f));
        sQ[dc][qq * 4 + 2] = make_uint2(f2tf(v0.z * 0.125f), f2tf(v1.z * 0.125f));
        sQ[dc][qq * 4 + 3] = make_uint2(f2tf(v0.w * 0.125f), f2tf(v1.w * 0.125f));
    }

    float o[8][4];
#pragma unroll
    for (int nb = 0; nb < 8; nb++)
#pragma unroll
        for (int q = 0; q < 4; q++) o[nb][q] = 0.f;
    float mrow[2] = {-1e30f, -1e30f};
    float lrow[2] = {0.f, 0.f};

    const int t0 = max(0, q0 - WINDOW) >> 6;
    const int t1 = q0 >> 6;
    const bool hasLeft = (q0 >= WINDOW);

    for (int t = t0; t <= t1; t++) {
        const int j0 = t << 6;

        // load K tile
#pragma unroll
        for (int it = 0; it < 4; it++) {
            const int item = it * 128 + tid;
            const int dc = item & 7, kk = item >> 3;
            const float* p = g_K + ((size_t)(b * S + j0 + kk)) * 512 + kvh * 64 + dc * 8;
            const float4 v0 = *(const float4*)p;
            const float4 v1 = *(const float4*)(p + 4);
            sKV[dc][kk * 4 + 0] = make_uint2(f2tf(v0.x), f2tf(v1.x));
            sKV[dc][kk * 4 + 1] = make_uint2(f2tf(v0.y), f2tf(v1.y));
            sKV[dc][kk * 4 + 2] = make_uint2(f2tf(v0.z), f2tf(v1.z));
            sKV[dc][kk * 4 + 3] = make_uint2(f2tf(v0.w), f2tf(v1.w));
        }
        __syncthreads();

        // S = (Q/8) K^T via MMA
        float s[8][4];
#pragma unroll
        for (int nb = 0; nb < 8; nb++)
#pragma unroll
            for (int q = 0; q < 4; q++) s[nb][q] = 0.f;
#pragma unroll
        for (int kc = 0; kc < 8; kc++) {
            const uint2 alo = sQ[kc][warp * 64 + lane];
            const uint2 ahi = sQ[kc][warp * 64 + 32 + lane];
#pragma unroll
            for (int nb = 0; nb < 8; nb++) {
                const uint2 bf = sKV[kc][nb * 32 + lane];
                mma_tf32(s[nb], alo.x, ahi.x, alo.y, ahi.y, bf.x, bf.y);
            }
        }

        // masks (edge tiles only)
        if (t == t1) {
#pragma unroll
            for (int nb = 0; nb < 8; nb++) {
                const int c0 = nb * 8 + 2 * cq;
                if (c0 > r0)         s[nb][0] = -1e30f;
                if (c0 + 1 > r0)     s[nb][1] = -1e30f;
                if (c0 > r0 + 8)     s[nb][2] = -1e30f;
                if (c0 + 1 > r0 + 8) s[nb][3] = -1e30f;
            }
        }
        if (hasLeft && t == t0) {
#pragma unroll
            for (int nb = 0; nb < 8; nb++) {
                const int c0 = nb * 8 + 2 * cq;
                if (c0 < r0)         s[nb][0] = -1e30f;
                if (c0 + 1 < r0)     s[nb][1] = -1e30f;
                if (c0 < r0 + 8)     s[nb][2] = -1e30f;
                if (c0 + 1 < r0 + 8) s[nb][3] = -1e30f;
            }
        }

        // online softmax (two row-halves per thread)
#pragma unroll
        for (int rh = 0; rh < 2; rh++) {
            float rm = -1e30f;
#pragma unroll
            for (int nb = 0; nb < 8; nb++)
                rm = fmaxf(rm, fmaxf(s[nb][2 * rh], s[nb][2 * rh + 1]));
            rm = fmaxf(rm, __shfl_xor_sync(0xffffffffu, rm, 1));
            rm = fmaxf(rm, __shfl_xor_sync(0xffffffffu, rm, 2));
            const float mn = fmaxf(mrow[rh], rm);
            const float sc = __expf(mrow[rh] - mn);
            mrow[rh] = mn;
            float ps = 0.f;
            const int rr = r0 + 8 * rh;
#pragma unroll
            for (int nb = 0; nb < 8; nb++) {
                const float p0 = __expf(s[nb][2 * rh] - mn);
                const float p1 = __expf(s[nb][2 * rh + 1] - mn);
                ps += p0 + p1;
                *(float2*)&sP[rr][nb * 8 + 2 * cq] = make_float2(p0, p1);
                o[nb][2 * rh]     *= sc;
                o[nb][2 * rh + 1] *= sc;
            }
            ps += __shfl_xor_sync(0xffffffffu, ps, 1);
            ps += __shfl_xor_sync(0xffffffffu, ps, 2);
            lrow[rh] = lrow[rh] * sc + ps;
        }
        __syncthreads();   // QK reads of sKV done

        // load V tile (pairs over keys)
#pragma unroll
        for (int it = 0; it < 4; it++) {
            const int item = it * 128 + tid;
            const int dg = item & 15, c = (item >> 4) & 3, kc = item >> 6;
            const float* p = g_V + ((size_t)(b * S + j0 + kc * 8 + c)) * 512 + kvh * 64 + dg * 4;
            const float4 v0 = *(const float4*)p;
            const float4 v1 = *(const float4*)(p + 4 * 512);
            sKV[kc][(dg * 4 + 0) * 4 + c] = make_uint2(f2tf(v0.x), f2tf(v1.x));
            sKV[kc][(dg * 4 + 1) * 4 + c] = make_uint2(f2tf(v0.y), f2tf(v1.y));
            sKV[kc][(dg * 4 + 2) * 4 + c] = make_uint2(f2tf(v0.z), f2tf(v1.z));
            sKV[kc][(dg * 4 + 3) * 4 + c] = make_uint2(f2tf(v0.w), f2tf(v1.w));
        }
        __syncthreads();

        // O += P V via MMA
#pragma unroll
        for (int kc = 0; kc < 8; kc++) {
            const int cc = kc * 8 + cq;
            const uint32_t a0 = f2tf(sP[r0][cc]);
            const uint32_t a1 = f2tf(sP[r0 + 8][cc]);
            const uint32_t a2 = f2tf(sP[r0][cc + 4]);
            const uint32_t a3 = f2tf(sP[r0 + 8][cc + 4]);
#pragma unroll
            for (int nb = 0; nb < 8; nb++) {
                const uint2 bf = sKV[kc][nb * 32 + lane];
                mma_tf32(o[nb], a0, a1, a2, a3, bf.x, bf.y);
            }
        }
        __syncthreads();   // before next tile overwrites sKV
    }

    // write O (rows r0, r0+8)
    const float i0 = 1.f / lrow[0];
    const float i1 = 1.f / lrow[1];
    float* O0 = g_O + ((size_t)(b * S + q0 + r0)) * 1024 + h * 64;
    float* O1 = O0 + 8 * 1024;
#pragma unroll
    for (int nb = 0; nb < 8; nb++) {
        *(float2*)&O0[nb * 8 + 2 * cq] = make_float2(o[nb][0] * i0, o[nb][1] * i0);
        *(float2*)&O1[nb * 8 + 2 * cq] = make_float2(o[nb][2] * i1, o[nb][3] * i1);
    }
}

extern "C" void kernel_launch(void* const* d_in, const int* in_sizes, int n_in,
                              void* d_out, int out_size)
{
    const float* X  = (const float*)d_in[0];
    const float* Wq = (const float*)d_in[1];
    const float* Wk = (const float*)d_in[2];
    const float* Wv = (const float*)d_in[3];
    const float* Wo = (const float*)d_in[4];
    float* out = (float*)d_out;

    rope_init_kernel<<<256, 256>>>();
    qkv_tf32_kernel<<<dim3(16, 32), 256>>>(X, Wq, Wk, Wv);
    rope_apply_kernel<<<(M_TOT * 768) / 256, 256>>>();
    attn_kernel<<<dim3(S / 64, Bsz * H), 128>>>();
    outproj_tf32_kernel<<<dim3(8, 32), 256>>>(Wo, out);
}

// round 10
// speedup vs baseline: 1.8712x; 1.8712x over previous
#include <cuda_runtime.h>
#include <cuda_bf16.h>
#include <math.h>
#include <stdint.h>

#define Bsz 2
#define S 2048
#define H 16
#define KV 8
#define HD 64
#define WINDOW 512
#define M_TOT (Bsz * S)      // 4096

__device__ float g_Q[M_TOT * (H * HD)];    // [b*s, 1024]
__device__ float g_K[M_TOT * (KV * HD)];   // [b*s, 512]
__device__ float g_V[M_TOT * (KV * HD)];
__device__ float g_O[M_TOT * (H * HD)];
__device__ float2 g_rope[S * 32];          // (cos,sin) per (t,f)

__device__ __forceinline__ uint32_t f2tf(float f) {
    uint32_t r;
    asm("cvt.rna.tf32.f32 %0, %1;" : "=r"(r) : "f"(f));
    return r;
}

__device__ __forceinline__ void mma_tf32(float c[4],
    uint32_t a0, uint32_t a1, uint32_t a2, uint32_t a3, uint32_t b0, uint32_t b1) {
    asm volatile(
        "mma.sync.aligned.m16n8k8.row.col.f32.tf32.tf32.f32 "
        "{%0,%1,%2,%3}, {%4,%5,%6,%7}, {%8,%9}, {%0,%1,%2,%3};"
        : "+f"(c[0]), "+f"(c[1]), "+f"(c[2]), "+f"(c[3])
        : "r"(a0), "r"(a1), "r"(a2), "r"(a3), "r"(b0), "r"(b1));
}

__device__ __forceinline__ void cp_async16(uint32_t dst_smem, const void* src) {
    asm volatile("cp.async.cg.shared.global [%0], [%1], 16;"
                 :: "r"(dst_smem), "l"(src) : "memory");
}
__device__ __forceinline__ void cp_commit() {
    asm volatile("cp.async.commit_group;" ::: "memory");
}
__device__ __forceinline__ void cp_wait0() {
    asm volatile("cp.async.wait_group 0;" ::: "memory");
}

// ---------------------------------------------------------------------------
// RoPE table + in-place apply
// ---------------------------------------------------------------------------
__global__ void rope_init_kernel() {
    const int idx = blockIdx.x * 256 + threadIdx.x;  // 65536
    const int t = idx >> 5, f = idx & 31;
    const float invf = expf(-logf(10000.0f) * (float)f * (1.0f / 32.0f));
    float sv, cv;
    sincosf((float)t * invf, &sv, &cv);
    g_rope[idx] = make_float2(cv, sv);
}

__global__ __launch_bounds__(256) void rope_apply_kernel() {
    const int idx = blockIdx.x * 256 + threadIdx.x;
    float* buf; int ld, p;
    if (idx < M_TOT * 512) { buf = g_Q; ld = 1024; p = idx; }
    else                   { buf = g_K; ld = 512;  p = idx - M_TOT * 512; }
    const int pph = ld >> 1;
    const int row = p / pph;
    const int q = p - row * pph;
    const int h = q >> 5, f = q & 31;
    const int t = row & (S - 1);
    float* base = buf + (size_t)row * ld + h * 64 + f;
    const float x = base[0], y = base[32];
    const float2 cs = g_rope[t * 32 + f];
    base[0]  = x * cs.x - y * cs.y;
    base[32] = y * cs.x + x * cs.y;
}

// ---------------------------------------------------------------------------
// tf32 GEMM core (unchanged): 128x128 tile, BK=16, 256 threads
// ---------------------------------------------------------------------------
__device__ __forceinline__ void gemm_tf32_core(
    const float* __restrict__ A0,
    const float* __restrict__ Bp, int ldb, int colbase,
    uint2 (*sA)[2][512], uint2 (*sB)[2][512],
    float c[4][4][4])
{
    const int tid = threadIdx.x, lane = tid & 31, warp = tid >> 5;
    const int wm = warp >> 2, wn = warp & 3;

#pragma unroll
    for (int m = 0; m < 4; m++)
#pragma unroll
        for (int n = 0; n < 4; n++)
#pragma unroll
            for (int q = 0; q < 4; q++) c[m][n][q] = 0.f;

    const int am = tid >> 1, akc = tid & 1;
    const float* ap = A0 + (size_t)am * 1024 + akc * 8;
    const int bc = tid & 3, bkc = (tid >> 2) & 1, bn = (tid >> 3) * 4;
    const float* bp = Bp + (size_t)(bkc * 8 + bc) * ldb + colbase + bn;

    float la[8], lb[8];
#define LOAD_G(k0) do { \
        float4 a0_ = *(const float4*)(ap + (k0)); \
        float4 a1_ = *(const float4*)(ap + (k0) + 4); \
        la[0]=a0_.x; la[1]=a0_.y; la[2]=a0_.z; la[3]=a0_.w; \
        la[4]=a1_.x; la[5]=a1_.y; la[6]=a1_.z; la[7]=a1_.w; \
        float4 b0_ = *(const float4*)(bp + (size_t)(k0) * ldb); \
        float4 b1_ = *(const float4*)(bp + (size_t)((k0) + 4) * ldb); \
        lb[0]=b0_.x; lb[1]=b0_.y; lb[2]=b0_.z; lb[3]=b0_.w; \
        lb[4]=b1_.x; lb[5]=b1_.y; lb[6]=b1_.z; lb[7]=b1_.w; \
    } while (0)
#define STS_T(st) do { \
        uint2* a_ = sA[st][akc] + am * 4; \
        a_[0] = make_uint2(f2tf(la[0]), f2tf(la[4])); \
        a_[1] = make_uint2(f2tf(la[1]), f2tf(la[5])); \
        a_[2] = make_uint2(f2tf(la[2]), f2tf(la[6])); \
        a_[3] = make_uint2(f2tf(la[3]), f2tf(la[7])); \
        uint2* b_ = sB[st][bkc]; \
        b_[(bn + 0) * 4 + bc] = make_uint2(f2tf(lb[0]), f2tf(lb[4])); \
        b_[(bn + 1) * 4 + bc] = make_uint2(f2tf(lb[1]), f2tf(lb[5])); \
        b_[(bn + 2) * 4 + bc] = make_uint2(f2tf(lb[2]), f2tf(lb[6])); \
        b_[(bn + 3) * 4 + bc] = make_uint2(f2tf(lb[3]), f2tf(lb[7])); \
    } while (0)

    LOAD_G(0);
    STS_T(0);
    __syncthreads();

    for (int kt = 0; kt < 64; kt++) {
        const int st = kt & 1;
        if (kt < 63) LOAD_G((kt + 1) * 16);
#pragma unroll
        for (int kc = 0; kc < 2; kc++) {
            const uint2* a = sA[st][kc];
            const uint2* b = sB[st][kc];
            uint2 alo[4], ahi[4], bf[4];
#pragma unroll
            for (int m = 0; m < 4; m++) {
                alo[m] = a[wm * 256 + m * 64 + lane];
                ahi[m] = a[wm * 256 + m * 64 + 32 + lane];
            }
#pragma unroll
            for (int n = 0; n < 4; n++)
                bf[n] = b[wn * 128 + n * 32 + lane];
#pragma unroll
            for (int m = 0; m < 4; m++)
#pragma unroll
                for (int n = 0; n < 4; n++)
                    mma_tf32(c[m][n], alo[m].x, ahi[m].x, alo[m].y, ahi[m].y,
                             bf[n].x, bf[n].y);
        }
        if (kt < 63) STS_T(st ^ 1);
        __syncthreads();
    }
#undef LOAD_G
#undef STS_T
}

__device__ __forceinline__ void gemm_store(
    float* dst, int dld, int mrow0, int colbase, float c[4][4][4])
{
    const int lane = threadIdx.x & 31, warp = threadIdx.x >> 5;
    const int wm = warp >> 2, wn = warp & 3;
#pragma unroll
    for (int m = 0; m < 4; m++) {
        const int r0 = mrow0 + wm * 64 + m * 16 + (lane >> 2);
#pragma unroll
        for (int n = 0; n < 4; n++) {
            const int gc = colbase + wn * 32 + n * 8 + 2 * (lane & 3);
            *(float2*)&dst[(size_t)r0 * dld + gc]       = make_float2(c[m][n][0], c[m][n][1]);
            *(float2*)&dst[(size_t)(r0 + 8) * dld + gc] = make_float2(c[m][n][2], c[m][n][3]);
        }
    }
}

__global__ __launch_bounds__(256) void qkv_tf32_kernel(
    const float* __restrict__ X, const float* __restrict__ Wq,
    const float* __restrict__ Wk, const float* __restrict__ Wv)
{
    __shared__ uint2 sA[2][2][512];
    __shared__ uint2 sB[2][2][512];
    const int bx = blockIdx.x;
    const int mrow0 = blockIdx.y * 128;
    const float* Bp; int ldb; float* dst; int dld; int colbase;
    if (bx < 8)       { Bp = Wq; ldb = 1024; dst = g_Q; dld = 1024; colbase = bx * 128; }
    else if (bx < 12) { Bp = Wk; ldb = 512;  dst = g_K; dld = 512;  colbase = (bx - 8) * 128; }
    else              { Bp = Wv; ldb = 512;  dst = g_V; dld = 512;  colbase = (bx - 12) * 128; }
    float c[4][4][4];
    gemm_tf32_core(X + (size_t)mrow0 * 1024, Bp, ldb, colbase, sA, sB, c);
    gemm_store(dst, dld, mrow0, colbase, c);
}

__global__ __launch_bounds__(256) void outproj_tf32_kernel(
    const float* __restrict__ Wo, float* __restrict__ out)
{
    __shared__ uint2 sA[2][2][512];
    __shared__ uint2 sB[2][2][512];
    const int colbase = blockIdx.x * 128;
    const int mrow0 = blockIdx.y * 128;
    float c[4][4][4];
    gemm_tf32_core(g_O + (size_t)mrow0 * 1024, Wo, 1024, colbase, sA, sB, c);
    gemm_store(out, 1024, mrow0, colbase, c);
}

// ---------------------------------------------------------------------------
// Attention v4: 128-row Q tile, 8 warps, cp.async double-buffered K/V,
// raw-f32 tf32 operands for K/V/P (HW truncation), 2 barriers per tile.
// Dynamic smem: sQ pairs 32KB | sK [64][68] | sV [64][72] | sP [128][68]
// ---------------------------------------------------------------------------
#define SK_STRIDE 68
#define SV_STRIDE 72
#define SP_STRIDE 68
#define SMEM_Q   32768
#define SMEM_K   (64 * SK_STRIDE * 4)          // 17408
#define SMEM_V   (64 * SV_STRIDE * 4)          // 18432
#define SMEM_P   (128 * SP_STRIDE * 4)         // 34816
#define SMEM_ATTN (SMEM_Q + SMEM_K + SMEM_V + SMEM_P)  // 103424

__global__ __launch_bounds__(256, 2) void attn_kernel()
{
    extern __shared__ char smem[];
    uint2* sQp = (uint2*)smem;
    float* sK = (float*)(smem + SMEM_Q);
    float* sV = (float*)(smem + SMEM_Q + SMEM_K);
    float* sP = (float*)(smem + SMEM_Q + SMEM_K + SMEM_V);

    const int bh = blockIdx.y;
    const int b = bh >> 4, h = bh & 15, kvh = h >> 1;
    const int q0 = blockIdx.x * 128;
    const int tid = threadIdx.x;
    const int lane = tid & 31, warp = tid >> 5;
    const int quad = lane >> 2, cq = lane & 3;
    const int r0 = warp * 16 + quad;           // rows r0 and r0+8 owned

    const uint32_t sK_u = (uint32_t)__cvta_generic_to_shared(sK);
    const uint32_t sV_u = (uint32_t)__cvta_generic_to_shared(sV);

    const int t0 = max(0, q0 - WINDOW) >> 6;
    const int t1 = (q0 >> 6) + 1;

    const float* Kbase = g_K + ((size_t)b * S) * 512 + kvh * 64;
    const float* Vbase = g_V + ((size_t)b * S) * 512 + kvh * 64;

    const int ldrow = tid >> 4;        // 0..15 base row for 16B-chunk loads
    const int ldchk = (tid & 15) * 4;  // float offset of 16B chunk

#define CP_K(T) do { \
        const int j0_ = (T) << 6; \
        _Pragma("unroll") \
        for (int ps = 0; ps < 4; ps++) { \
            const int row = ps * 16 + ldrow; \
            cp_async16(sK_u + (row * SK_STRIDE + ldchk) * 4, \
                       Kbase + (size_t)(j0_ + row) * 512 + ldchk); \
        } \
        cp_commit(); \
    } while (0)
#define CP_V(T) do { \
        const int j0_ = (T) << 6; \
        _Pragma("unroll") \
        for (int ps = 0; ps < 4; ps++) { \
            const int row = ps * 16 + ldrow; \
            cp_async16(sV_u + (row * SV_STRIDE + ldchk) * 4, \
                       Vbase + (size_t)(j0_ + row) * 512 + ldchk); \
        } \
        cp_commit(); \
    } while (0)

    // preload K(t0), stage Q (pairs, rna tf32, prescaled) meanwhile
    CP_K(t0);
#pragma unroll
    for (int it = 0; it < 4; it++) {
        const int item = it * 256 + tid;
        const int dc = item & 7, qq = item >> 3;
        const float* p = g_Q + ((size_t)(b * S + q0 + qq)) * 1024 + h * 64 + dc * 8;
        const float4 v0 = *(const float4*)p;
        const float4 v1 = *(const float4*)(p + 4);
        sQp[dc * 512 + qq * 4 + 0] = make_uint2(f2tf(v0.x * 0.125f), f2tf(v1.x * 0.125f));
        sQp[dc * 512 + qq * 4 + 1] = make_uint2(f2tf(v0.y * 0.125f), f2tf(v1.y * 0.125f));
        sQp[dc * 512 + qq * 4 + 2] = make_uint2(f2tf(v0.z * 0.125f), f2tf(v1.z * 0.125f));
        sQp[dc * 512 + qq * 4 + 3] = make_uint2(f2tf(v0.w * 0.125f), f2tf(v1.w * 0.125f));
    }
    cp_wait0();
    __syncthreads();

    float o[8][4];
#pragma unroll
    for (int nb = 0; nb < 8; nb++)
#pragma unroll
        for (int q = 0; q < 4; q++) o[nb][q] = 0.f;
    float mrow[2] = {-1e30f, -1e30f};
    float lrow[2] = {0.f, 0.f};

    for (int t = t0; t <= t1; t++) {
        const int j0 = t << 6;

        CP_V(t);   // overlaps QK + softmax

        // S = (Q/8) K^T
        float s[8][4];
#pragma unroll
        for (int nb = 0; nb < 8; nb++)
#pragma unroll
            for (int q = 0; q < 4; q++) s[nb][q] = 0.f;
#pragma unroll
        for (int kc = 0; kc < 8; kc++) {
            const uint2 alo = sQp[kc * 512 + warp * 64 + lane];
            const uint2 ahi = sQp[kc * 512 + warp * 64 + 32 + lane];
            const float* kr = sK + kc * 8 + cq;
#pragma unroll
            for (int nb = 0; nb < 8; nb++) {
                const int kk = nb * 8 + quad;
                const uint32_t b0 = __float_as_uint(kr[kk * SK_STRIDE]);
                const uint32_t b1 = __float_as_uint(kr[kk * SK_STRIDE + 4]);
                mma_tf32(s[nb], alo.x, ahi.x, alo.y, ahi.y, b0, b1);
            }
        }

        // masks on edge tiles (exact global window)
        if (t - t0 <= 1 || t1 - t <= 1) {
            const int i0g = q0 + r0, i1g = i0g + 8;
#pragma unroll
            for (int nb = 0; nb < 8; nb++) {
                const int c0 = j0 + nb * 8 + 2 * cq;
                if (!(c0     <= i0g && c0     >= i0g - WINDOW)) s[nb][0] = -1e30f;
                if (!(c0 + 1 <= i0g && c0 + 1 >= i0g - WINDOW)) s[nb][1] = -1e30f;
                if (!(c0     <= i1g && c0     >= i1g - WINDOW)) s[nb][2] = -1e30f;
                if (!(c0 + 1 <= i1g && c0 + 1 >= i1g - WINDOW)) s[nb][3] = -1e30f;
            }
        }

        // online softmax, write P
#pragma unroll
        for (int rh = 0; rh < 2; rh++) {
            float rm = -1e30f;
#pragma unroll
            for (int nb = 0; nb < 8; nb++)
                rm = fmaxf(rm, fmaxf(s[nb][2 * rh], s[nb][2 * rh + 1]));
            rm = fmaxf(rm, __shfl_xor_sync(0xffffffffu, rm, 1));
            rm = fmaxf(rm, __shfl_xor_sync(0xffffffffu, rm, 2));
            const float mn = fmaxf(mrow[rh], rm);
            const float sc = __expf(mrow[rh] - mn);
            mrow[rh] = mn;
            float ps = 0.f;
            const int rr = r0 + 8 * rh;
#pragma unroll
            for (int nb = 0; nb < 8; nb++) {
                const float p0 = __expf(s[nb][2 * rh] - mn);
                const float p1 = __expf(s[nb][2 * rh + 1] - mn);
                ps += p0 + p1;
                *(float2*)&sP[rr * SP_STRIDE + nb * 8 + 2 * cq] = make_float2(p0, p1);
                o[nb][2 * rh]     *= sc;
                o[nb][2 * rh + 1] *= sc;
            }
            ps += __shfl_xor_sync(0xffffffffu, ps, 1);
            ps += __shfl_xor_sync(0xffffffffu, ps, 2);
            lrow[rh] = lrow[rh] * sc + ps;
        }

        cp_wait0();        // V(t) landed
        __syncthreads();   // all V visible; all QK reads of sK done

        if (t < t1) CP_K(t + 1);   // overlaps PV

        // O += P V
#pragma unroll
        for (int kc = 0; kc < 8; kc++) {
            const int cc = kc * 8 + cq;
            const uint32_t a0 = __float_as_uint(sP[r0 * SP_STRIDE + cc]);
            const uint32_t a1 = __float_as_uint(sP[(r0 + 8) * SP_STRIDE + cc]);
            const uint32_t a2 = __float_as_uint(sP[r0 * SP_STRIDE + cc + 4]);
            const uint32_t a3 = __float_as_uint(sP[(r0 + 8) * SP_STRIDE + cc + 4]);
            const float* vr = sV + (kc * 8 + cq) * SV_STRIDE + quad;
#pragma unroll
            for (int nb = 0; nb < 8; nb++) {
                const uint32_t b0 = __float_as_uint(vr[nb * 8]);
                const uint32_t b1 = __float_as_uint(vr[4 * SV_STRIDE + nb * 8]);
                mma_tf32(o[nb], a0, a1, a2, a3, b0, b1);
            }
        }

        cp_wait0();        // K(t+1) landed
        __syncthreads();   // all K visible; all PV reads of sV/sP done
    }

    // write O (rows r0, r0+8)
    const float i0 = 1.f / lrow[0];
    const float i1 = 1.f / lrow[1];
    float* O0 = g_O + ((size_t)(b * S + q0 + r0)) * 1024 + h * 64;
    float* O1 = O0 + 8 * 1024;
#pragma unroll
    for (int nb = 0; nb < 8; nb++) {
        *(float2*)&O0[nb * 8 + 2 * cq] = make_float2(o[nb][0] * i0, o[nb][1] * i0);
        *(float2*)&O1[nb * 8 + 2 * cq] = make_float2(o[nb][2] * i1, o[nb][3] * i1);
    }
}

extern "C" void kernel_launch(void* const* d_in, const int* in_sizes, int n_in,
                              void* d_out, int out_size)
{
    const float* X  = (const float*)d_in[0];
    const float* Wq = (const float*)d_in[1];
    const float* Wk = (const float*)d_in[2];
    const float* Wv = (const float*)d_in[3];
    const float* Wo = (const float*)d_in[4];
    float* out = (float*)d_out;

    cudaFuncSetAttribute(attn_kernel,
                         cudaFuncAttributeMaxDynamicSharedMemorySize, SMEM_ATTN);

    rope_init_kernel<<<256, 256>>>();
    qkv_tf32_kernel<<<dim3(16, 32), 256>>>(X, Wq, Wk, Wv);
    rope_apply_kernel<<<(M_TOT * 768) / 256, 256>>>();
    attn_kernel<<<dim3(S / 128, Bsz * H), 256, SMEM_ATTN>>>();
    outproj_tf32_kernel<<<dim3(8, 32), 256>>>(Wo, out);
}